// round 1
// baseline (speedup 1.0000x reference)
#include <cuda_runtime.h>
#include <math.h>

// Problem constants
#define BB 2
#define QQ 1024
#define KK 2048
#define MM 1024
#define EE 1024
#define HH 32
#define HD 32
#define LTOT (KK + MM)   // 3072

// -------- scratch (allocation-free: __device__ globals) --------
__device__ float g_Qp[BB * QQ * EE];   // projected q     (B,Q,E)
__device__ float g_Kp[BB * KK * EE];   // projected k     (B,K,E)
__device__ float g_Vp[BB * KK * EE];   // projected v     (B,K,E)
__device__ float g_MK[BB * MM * EE];   // projected mem-k (B,M,E)
__device__ float g_MV[BB * MM * EE];   // projected mem-v (B,M,E)
__device__ float g_O [BB * QQ * EE];   // attention out   (B,Q,E)

// ============================================================
// GEMM (NT): Y[r, n] = sum_e X[r, e] * W[n, e] + bias[n]
// Fixed inner dims: E = N = 1024. Tile 64x64x16, 256 threads, 4x4 micro-tile.
// ============================================================
__global__ __launch_bounds__(256) void gemm_nt(
    const float* __restrict__ X, const float* __restrict__ W,
    const float* __restrict__ bias, float* __restrict__ Y)
{
    __shared__ float Xs[16][65];
    __shared__ float Ws[16][65];

    const int bm = blockIdx.y * 64;
    const int bn = blockIdx.x * 64;
    const int t  = threadIdx.x;
    const int tx = t & 15;        // output col group
    const int ty = t >> 4;        // output row group
    const int lr = t >> 2;        // load row within 64
    const int lc = (t & 3) << 2;  // load col within 16 (float4)

    const float* xp = X + (size_t)(bm + lr) * EE + lc;
    const float* wp = W + (size_t)(bn + lr) * EE + lc;

    float acc[4][4] = {};

    for (int k0 = 0; k0 < EE; k0 += 16) {
        float4 xv = *(const float4*)(xp + k0);
        float4 wv = *(const float4*)(wp + k0);
        Xs[lc + 0][lr] = xv.x; Xs[lc + 1][lr] = xv.y;
        Xs[lc + 2][lr] = xv.z; Xs[lc + 3][lr] = xv.w;
        Ws[lc + 0][lr] = wv.x; Ws[lc + 1][lr] = wv.y;
        Ws[lc + 2][lr] = wv.z; Ws[lc + 3][lr] = wv.w;
        __syncthreads();

        #pragma unroll
        for (int k = 0; k < 16; k++) {
            float a[4], b[4];
            #pragma unroll
            for (int i = 0; i < 4; i++) a[i] = Xs[k][ty * 4 + i];
            #pragma unroll
            for (int j = 0; j < 4; j++) b[j] = Ws[k][tx * 4 + j];
            #pragma unroll
            for (int i = 0; i < 4; i++)
                #pragma unroll
                for (int j = 0; j < 4; j++)
                    acc[i][j] += a[i] * b[j];
        }
        __syncthreads();
    }

    #pragma unroll
    for (int i = 0; i < 4; i++) {
        size_t row = (size_t)(bm + ty * 4 + i) * EE + bn;
        #pragma unroll
        for (int j = 0; j < 4; j++)
            Y[row + tx * 4 + j] = acc[i][j] + bias[bn + tx * 4 + j];
    }
}

// ============================================================
// Flash attention over concatenated [K | M] sequence.
// Block: (b, h, 64-query tile). 256 threads.
// ============================================================
__global__ __launch_bounds__(256) void attn_kernel()
{
    __shared__ float Qs[64][33];
    __shared__ float Ks[64][33];
    __shared__ float Vs[64][33];
    __shared__ float Ss[64][65];
    __shared__ float mrow[64], lrow[64], frow[64];

    const int q0 = blockIdx.x * 64;
    const int bh = blockIdx.y;
    const int b  = bh >> 5;        // H = 32
    const int h  = bh & 31;
    const int t  = threadIdx.x;
    const float scale = 0.17677669529663687f;  // 1/sqrt(32)

    // Load + pre-scale Q tile
    {
        const int col = t & 31;
        const int r0  = t >> 5;
        #pragma unroll
        for (int it = 0; it < 8; it++) {
            int r = r0 + it * 8;
            Qs[r][col] = g_Qp[(size_t)(b * QQ + q0 + r) * EE + h * HD + col] * scale;
        }
    }
    if (t < 64) { mrow[t] = -1e30f; lrow[t] = 0.f; }

    // Output accumulators: thread owns 2 query rows x 4 head-dims
    const int rq = t >> 3;          // 0..31 -> rows 2*rq, 2*rq+1
    const int cd = (t & 7) << 2;    // 0,4,...,28
    float o[2][4] = {};

    __syncthreads();

    for (int kt = 0; kt < LTOT / 64; kt++) {
        const int l0 = kt * 64;

        // ---- load K/V tile (either from k/v projections or memory projections)
        {
            const int col = t & 31;
            const int r0  = t >> 5;
            const float *ksrc, *vsrc;
            if (l0 < KK) {
                size_t base = (size_t)(b * KK + l0) * EE + h * HD;
                ksrc = g_Kp + base; vsrc = g_Vp + base;
            } else {
                size_t base = (size_t)(b * MM + (l0 - KK)) * EE + h * HD;
                ksrc = g_MK + base; vsrc = g_MV + base;
            }
            #pragma unroll
            for (int it = 0; it < 8; it++) {
                int r = r0 + it * 8;
                Ks[r][col] = ksrc[(size_t)r * EE + col];
                Vs[r][col] = vsrc[(size_t)r * EE + col];
            }
        }
        __syncthreads();

        // ---- S = (Q*scale) . K^T : 16x16 thread grid, 4x4 each
        {
            const int tx = t & 15, ty = t >> 4;
            float acc[4][4] = {};
            #pragma unroll
            for (int d = 0; d < 32; d++) {
                float a[4], bb[4];
                #pragma unroll
                for (int i = 0; i < 4; i++) a[i] = Qs[ty * 4 + i][d];
                #pragma unroll
                for (int j = 0; j < 4; j++) bb[j] = Ks[tx * 4 + j][d];
                #pragma unroll
                for (int i = 0; i < 4; i++)
                    #pragma unroll
                    for (int j = 0; j < 4; j++)
                        acc[i][j] += a[i] * bb[j];
            }
            #pragma unroll
            for (int i = 0; i < 4; i++)
                #pragma unroll
                for (int j = 0; j < 4; j++)
                    Ss[ty * 4 + i][tx * 4 + j] = acc[i][j];
        }
        __syncthreads();

        // ---- online softmax: 4 lanes per row (16 cols each)
        {
            const int r = t >> 2;
            const int seg = (t & 3) * 16;
            float s[16];
            float mx = -1e30f;
            #pragma unroll
            for (int i = 0; i < 16; i++) {
                s[i] = Ss[r][seg + i];
                mx = fmaxf(mx, s[i]);
            }
            mx = fmaxf(mx, __shfl_xor_sync(0xffffffffu, mx, 1));
            mx = fmaxf(mx, __shfl_xor_sync(0xffffffffu, mx, 2));
            float mold = mrow[r];
            float mnew = fmaxf(mold, mx);
            float ls = 0.f;
            #pragma unroll
            for (int i = 0; i < 16; i++) {
                float p = __expf(s[i] - mnew);
                Ss[r][seg + i] = p;
                ls += p;
            }
            ls += __shfl_xor_sync(0xffffffffu, ls, 1);
            ls += __shfl_xor_sync(0xffffffffu, ls, 2);
            if ((t & 3) == 0) {
                float f = __expf(mold - mnew);   // 0 on first tile (mold = -1e30)
                frow[r] = f;
                lrow[r] = lrow[r] * f + ls;
                mrow[r] = mnew;
            }
        }
        __syncthreads();

        // ---- O = O*f + P . V
        {
            const int r0 = rq * 2;
            float f0 = frow[r0], f1 = frow[r0 + 1];
            #pragma unroll
            for (int c = 0; c < 4; c++) { o[0][c] *= f0; o[1][c] *= f1; }
            #pragma unroll 4
            for (int j = 0; j < 64; j++) {
                float p0 = Ss[r0][j], p1 = Ss[r0 + 1][j];
                #pragma unroll
                for (int c = 0; c < 4; c++) {
                    float v = Vs[j][cd + c];
                    o[0][c] += p0 * v;
                    o[1][c] += p1 * v;
                }
            }
        }
        __syncthreads();   // protect Ks/Vs/Ss before next tile's loads
    }

    // ---- normalize + write
    {
        const int r0 = rq * 2;
        float inv0 = 1.f / lrow[r0];
        float inv1 = 1.f / lrow[r0 + 1];
        size_t base = (size_t)(b * QQ + q0 + r0) * EE + h * HD + cd;
        #pragma unroll
        for (int c = 0; c < 4; c++) {
            g_O[base + c]      = o[0][c] * inv0;
            g_O[base + EE + c] = o[1][c] * inv1;
        }
    }
}

// ============================================================
// launch
// ============================================================
extern "C" void kernel_launch(void* const* d_in, const int* in_sizes, int n_in,
                              void* d_out, int out_size)
{
    const float* query  = (const float*)d_in[0];
    const float* key    = (const float*)d_in[1];
    const float* value  = (const float*)d_in[2];
    const float* memory = (const float*)d_in[3];
    const float* Wq = (const float*)d_in[4];
    const float* bq = (const float*)d_in[5];
    const float* Wk = (const float*)d_in[6];
    const float* bk = (const float*)d_in[7];
    const float* Wv = (const float*)d_in[8];
    const float* bv = (const float*)d_in[9];
    const float* Wo = (const float*)d_in[10];
    const float* bo = (const float*)d_in[11];
    float* out = (float*)d_out;

    float *Qp, *Kp, *Vp, *MK, *MV, *O;
    cudaGetSymbolAddress((void**)&Qp, g_Qp);
    cudaGetSymbolAddress((void**)&Kp, g_Kp);
    cudaGetSymbolAddress((void**)&Vp, g_Vp);
    cudaGetSymbolAddress((void**)&MK, g_MK);
    cudaGetSymbolAddress((void**)&MV, g_MV);
    cudaGetSymbolAddress((void**)&O,  g_O);

    // Projections: rows = B*Q = 2048 (32 row-blocks) or B*K = 4096 (64 row-blocks)
    gemm_nt<<<dim3(16, 32), 256>>>(query,  Wq, bq, Qp);
    gemm_nt<<<dim3(16, 64), 256>>>(key,    Wk, bk, Kp);
    gemm_nt<<<dim3(16, 64), 256>>>(value,  Wv, bv, Vp);
    gemm_nt<<<dim3(16, 32), 256>>>(memory, Wk, bk, MK);
    gemm_nt<<<dim3(16, 32), 256>>>(memory, Wv, bv, MV);

    // Attention: (Q/64 = 16) x (B*H = 64)
    attn_kernel<<<dim3(16, 64), 256>>>();

    // Output projection
    gemm_nt<<<dim3(16, 32), 256>>>(O, Wo, bo, out);
}

// round 4
// speedup vs baseline: 1.6850x; 1.6850x over previous
#include <cuda_runtime.h>
#include <cuda_bf16.h>
#include <cstdint>
#include <math.h>

// Problem constants
#define BB 2
#define QQ 1024
#define KK 2048
#define MM 1024
#define EE 1024
#define HH 32
#define HD 32
#define LTOT (KK + MM)   // 3072

// -------- fp32 scratch --------
__device__ float g_Qp[BB * QQ * EE];
__device__ float g_Kp[BB * KK * EE];
__device__ float g_Vp[BB * KK * EE];
__device__ float g_MK[BB * MM * EE];
__device__ float g_MV[BB * MM * EE];
__device__ float g_O [BB * QQ * EE];

// -------- bf16-pair scratch --------
__device__ __nv_bfloat16 g_q_hi[BB*QQ*EE],  g_q_lo[BB*QQ*EE];
__device__ __nv_bfloat16 g_k_hi[BB*KK*EE],  g_k_lo[BB*KK*EE];
__device__ __nv_bfloat16 g_v_hi[BB*KK*EE],  g_v_lo[BB*KK*EE];
__device__ __nv_bfloat16 g_m_hi[BB*MM*EE],  g_m_lo[BB*MM*EE];
__device__ __nv_bfloat16 g_o_hi[BB*QQ*EE],  g_o_lo[BB*QQ*EE];
__device__ __nv_bfloat16 g_wq_hi[EE*EE], g_wq_lo[EE*EE];
__device__ __nv_bfloat16 g_wk_hi[EE*EE], g_wk_lo[EE*EE];
__device__ __nv_bfloat16 g_wv_hi[EE*EE], g_wv_lo[EE*EE];
__device__ __nv_bfloat16 g_wo_hi[EE*EE], g_wo_lo[EE*EE];

// ============================================================
// PTX helpers (baseline ISA: works on plain sm_103 target)
// ============================================================
__device__ __forceinline__ uint32_t smem_u32(const void* p) {
    uint32_t a;
    asm("{ .reg .u64 t; cvta.to.shared.u64 t, %1; cvt.u32.u64 %0, t; }" : "=r"(a) : "l"(p));
    return a;
}

__device__ __forceinline__ void cp_async16(uint32_t saddr, const void* gptr) {
    asm volatile("cp.async.cg.shared.global [%0], [%1], 16;" :: "r"(saddr), "l"(gptr) : "memory");
}
#define CP_COMMIT() asm volatile("cp.async.commit_group;" ::: "memory")
#define CP_WAIT(n)  asm volatile("cp.async.wait_group %0;" :: "n"(n) : "memory")

__device__ __forceinline__ void ldm_x4(uint32_t* r, uint32_t addr) {
    asm volatile("ldmatrix.sync.aligned.m8n8.x4.shared.b16 {%0,%1,%2,%3}, [%4];"
                 : "=r"(r[0]), "=r"(r[1]), "=r"(r[2]), "=r"(r[3]) : "r"(addr));
}

__device__ __forceinline__ void mma_bf16(float* d, const uint32_t* a, const uint32_t* b) {
    asm volatile(
        "mma.sync.aligned.m16n8k16.row.col.f32.bf16.bf16.f32 "
        "{%0,%1,%2,%3}, {%4,%5,%6,%7}, {%8,%9}, {%0,%1,%2,%3};"
        : "+f"(d[0]), "+f"(d[1]), "+f"(d[2]), "+f"(d[3])
        : "r"(a[0]), "r"(a[1]), "r"(a[2]), "r"(a[3]), "r"(b[0]), "r"(b[1]));
}

// ============================================================
// fp32 -> bf16 (hi, lo) split
// ============================================================
__global__ __launch_bounds__(256) void f32_to_bf16pair(
    const float* __restrict__ x, __nv_bfloat16* __restrict__ hi,
    __nv_bfloat16* __restrict__ lo)
{
    int i = blockIdx.x * 256 + threadIdx.x;
    float v = x[i];
    __nv_bfloat16 h = __float2bfloat16(v);
    hi[i] = h;
    lo[i] = __float2bfloat16(v - __bfloat162float(h));
}

// ============================================================
// HMMA GEMM (NT): Y[r,n] = sum_e A[r,e]*B[n,e] + bias[n]
// bf16 hi/lo 3-pass. Tile 128x128, K-chunk 32, 256 threads (8 warps 4x2),
// warp computes 32x64. cp.async double buffer.
// Smem row layout (per tile row): [hi k0..31 | lo k0..31] = 64 halves = 128B,
// 16B chunks XOR-swizzled: phys = log ^ (row & 7).
// ============================================================
#define GSTAGE 32768          // bytes per stage (A 16KB + B 16KB)
__global__ __launch_bounds__(256) void gemm_mma(
    const __nv_bfloat16* __restrict__ Ahi, const __nv_bfloat16* __restrict__ Alo,
    const __nv_bfloat16* __restrict__ Bhi, const __nv_bfloat16* __restrict__ Blo,
    const float* __restrict__ bias, float* __restrict__ Y)
{
    extern __shared__ char smem[];
    const uint32_t sbase = smem_u32(smem);
    const int t = threadIdx.x, wid = t >> 5, lane = t & 31;
    const int warp_m = wid & 3;          // 4 warps along M, 32 rows each
    const int warp_n = wid >> 2;         // 2 warps along N, 64 cols each
    const int tile_m = blockIdx.y * 128;
    const int tile_n = blockIdx.x * 128;

    float acc[2][8][4];
    #pragma unroll
    for (int i = 0; i < 2; i++)
        #pragma unroll
        for (int j = 0; j < 8; j++)
            #pragma unroll
            for (int k = 0; k < 4; k++) acc[i][j][k] = 0.f;

    // ---- async loader: thread t does 8 16B chunks per stage
    // slot = i*256 + t; buf = slot/1024 (0=A,1=B); w = slot%1024: row=w/8, log=w%8
    // log 0..3 -> hi halves log*8; log 4..7 -> lo halves (log-4)*8
    auto issue_stage = [&](int c, int st) {
        const uint32_t sb = sbase + st * GSTAGE;
        #pragma unroll
        for (int i = 0; i < 8; i++) {
            int slot = i * 256 + t;
            int buf = slot >> 10;
            int w = slot & 1023;
            int row = w >> 3, logc = w & 7;
            const __nv_bfloat16* src;
            int kh = c * 32 + (logc & 3) * 8;
            if (buf == 0)
                src = ((logc < 4) ? Ahi : Alo) + (size_t)(tile_m + row) * 1024 + kh;
            else
                src = ((logc < 4) ? Bhi : Blo) + (size_t)(tile_n + row) * 1024 + kh;
            uint32_t dst = sb + buf * 16384 + row * 128 + ((logc ^ (row & 7)) * 16);
            cp_async16(dst, src);
        }
        CP_COMMIT();
    };

    issue_stage(0, 0);

    const int q = lane >> 3, li = lane & 7;

    for (int c = 0; c < 32; c++) {
        const int st = c & 1;
        if (c + 1 < 32) { issue_stage(c + 1, st ^ 1); CP_WAIT(1); }
        else            { CP_WAIT(0); }
        __syncthreads();

        const uint32_t Ab = sbase + st * GSTAGE;
        const uint32_t Bb = Ab + 16384;

        #pragma unroll
        for (int ks = 0; ks < 2; ks++) {
            uint32_t ah[2][4], al[2][4], bh[8][2], bl[8][2];
            // A frags: m16k16 x4. lane q=0..3: rows mbase+(q&1)*8+li, chunk ks*2+(q>>1)
            #pragma unroll
            for (int mf = 0; mf < 2; mf++) {
                int row = warp_m * 32 + mf * 16 + (q & 1) * 8 + li;
                int lch = ks * 2 + (q >> 1);
                ldm_x4(ah[mf], Ab + row * 128 + ((lch ^ (row & 7)) * 16));
                lch += 4;
                ldm_x4(al[mf], Ab + row * 128 + ((lch ^ (row & 7)) * 16));
            }
            // B frags: pairs of n8 frags per x4. q: (q>>1) selects n-half, (q&1) selects k-chunk
            #pragma unroll
            for (int p = 0; p < 4; p++) {
                int row = warp_n * 64 + p * 16 + (q >> 1) * 8 + li;
                int lch = ks * 2 + (q & 1);
                uint32_t r4[4];
                ldm_x4(r4, Bb + row * 128 + ((lch ^ (row & 7)) * 16));
                bh[p * 2][0] = r4[0]; bh[p * 2][1] = r4[1];
                bh[p * 2 + 1][0] = r4[2]; bh[p * 2 + 1][1] = r4[3];
                lch += 4;
                ldm_x4(r4, Bb + row * 128 + ((lch ^ (row & 7)) * 16));
                bl[p * 2][0] = r4[0]; bl[p * 2][1] = r4[1];
                bl[p * 2 + 1][0] = r4[2]; bl[p * 2 + 1][1] = r4[3];
            }
            // 3-pass mma
            #pragma unroll
            for (int mf = 0; mf < 2; mf++)
                #pragma unroll
                for (int nf = 0; nf < 8; nf++) {
                    mma_bf16(acc[mf][nf], ah[mf], bh[nf]);
                    mma_bf16(acc[mf][nf], ah[mf], bl[nf]);
                    mma_bf16(acc[mf][nf], al[mf], bh[nf]);
                }
        }
        __syncthreads();
    }

    // ---- epilogue: D layout lane l -> rows base + l/4 (+8), cols 2*(l%4)+{0,1}
    #pragma unroll
    for (int mf = 0; mf < 2; mf++) {
        int r0 = tile_m + warp_m * 32 + mf * 16 + (lane >> 2);
        #pragma unroll
        for (int nf = 0; nf < 8; nf++) {
            int col = tile_n + warp_n * 64 + nf * 8 + (lane & 3) * 2;
            float b0 = __ldg(bias + col), b1 = __ldg(bias + col + 1);
            float2 v0 = make_float2(acc[mf][nf][0] + b0, acc[mf][nf][1] + b1);
            float2 v1 = make_float2(acc[mf][nf][2] + b0, acc[mf][nf][3] + b1);
            *(float2*)(Y + (size_t)r0 * 1024 + col)       = v0;
            *(float2*)(Y + (size_t)(r0 + 8) * 1024 + col) = v1;
        }
    }
}

// ============================================================
// Flash attention over concatenated [K | M] sequence (SIMT).
// ============================================================
__global__ __launch_bounds__(256) void attn_kernel()
{
    __shared__ float Qs[64][33];
    __shared__ float Ks[64][33];
    __shared__ float Vs[64][33];
    __shared__ float Ss[64][65];
    __shared__ float mrow[64], lrow[64], frow[64];

    const int q0 = blockIdx.x * 64;
    const int bh = blockIdx.y;
    const int b  = bh >> 5;
    const int h  = bh & 31;
    const int t  = threadIdx.x;
    const float scale = 0.17677669529663687f;

    {
        const int col = t & 31;
        const int r0  = t >> 5;
        #pragma unroll
        for (int it = 0; it < 8; it++) {
            int r = r0 + it * 8;
            Qs[r][col] = g_Qp[(size_t)(b * QQ + q0 + r) * EE + h * HD + col] * scale;
        }
    }
    if (t < 64) { mrow[t] = -1e30f; lrow[t] = 0.f; }

    const int rq = t >> 3;
    const int cd = (t & 7) << 2;
    float o[2][4] = {};

    __syncthreads();

    for (int kt = 0; kt < LTOT / 64; kt++) {
        const int l0 = kt * 64;
        {
            const int col = t & 31;
            const int r0  = t >> 5;
            const float *ksrc, *vsrc;
            if (l0 < KK) {
                size_t base = (size_t)(b * KK + l0) * EE + h * HD;
                ksrc = g_Kp + base; vsrc = g_Vp + base;
            } else {
                size_t base = (size_t)(b * MM + (l0 - KK)) * EE + h * HD;
                ksrc = g_MK + base; vsrc = g_MV + base;
            }
            #pragma unroll
            for (int it = 0; it < 8; it++) {
                int r = r0 + it * 8;
                Ks[r][col] = ksrc[(size_t)r * EE + col];
                Vs[r][col] = vsrc[(size_t)r * EE + col];
            }
        }
        __syncthreads();

        {
            const int tx = t & 15, ty = t >> 4;
            float acc[4][4] = {};
            #pragma unroll
            for (int d = 0; d < 32; d++) {
                float a[4], bb[4];
                #pragma unroll
                for (int i = 0; i < 4; i++) a[i] = Qs[ty * 4 + i][d];
                #pragma unroll
                for (int j = 0; j < 4; j++) bb[j] = Ks[tx * 4 + j][d];
                #pragma unroll
                for (int i = 0; i < 4; i++)
                    #pragma unroll
                    for (int j = 0; j < 4; j++)
                        acc[i][j] += a[i] * bb[j];
            }
            #pragma unroll
            for (int i = 0; i < 4; i++)
                #pragma unroll
                for (int j = 0; j < 4; j++)
                    Ss[ty * 4 + i][tx * 4 + j] = acc[i][j];
        }
        __syncthreads();

        {
            const int r = t >> 2;
            const int seg = (t & 3) * 16;
            float s[16];
            float mx = -1e30f;
            #pragma unroll
            for (int i = 0; i < 16; i++) {
                s[i] = Ss[r][seg + i];
                mx = fmaxf(mx, s[i]);
            }
            mx = fmaxf(mx, __shfl_xor_sync(0xffffffffu, mx, 1));
            mx = fmaxf(mx, __shfl_xor_sync(0xffffffffu, mx, 2));
            float mold = mrow[r];
            float mnew = fmaxf(mold, mx);
            float ls = 0.f;
            #pragma unroll
            for (int i = 0; i < 16; i++) {
                float p = __expf(s[i] - mnew);
                Ss[r][seg + i] = p;
                ls += p;
            }
            ls += __shfl_xor_sync(0xffffffffu, ls, 1);
            ls += __shfl_xor_sync(0xffffffffu, ls, 2);
            if ((t & 3) == 0) {
                float f = __expf(mold - mnew);
                frow[r] = f;
                lrow[r] = lrow[r] * f + ls;
                mrow[r] = mnew;
            }
        }
        __syncthreads();

        {
            const int r0 = rq * 2;
            float f0 = frow[r0], f1 = frow[r0 + 1];
            #pragma unroll
            for (int c = 0; c < 4; c++) { o[0][c] *= f0; o[1][c] *= f1; }
            #pragma unroll 4
            for (int j = 0; j < 64; j++) {
                float p0 = Ss[r0][j], p1 = Ss[r0 + 1][j];
                #pragma unroll
                for (int c = 0; c < 4; c++) {
                    float v = Vs[j][cd + c];
                    o[0][c] += p0 * v;
                    o[1][c] += p1 * v;
                }
            }
        }
        __syncthreads();
    }

    {
        const int r0 = rq * 2;
        float inv0 = 1.f / lrow[r0];
        float inv1 = 1.f / lrow[r0 + 1];
        size_t base = (size_t)(b * QQ + q0 + r0) * EE + h * HD + cd;
        #pragma unroll
        for (int c = 0; c < 4; c++) {
            g_O[base + c]      = o[0][c] * inv0;
            g_O[base + EE + c] = o[1][c] * inv1;
        }
    }
}

// ============================================================
// launch
// ============================================================
extern "C" void kernel_launch(void* const* d_in, const int* in_sizes, int n_in,
                              void* d_out, int out_size)
{
    const float* query  = (const float*)d_in[0];
    const float* key    = (const float*)d_in[1];
    const float* value  = (const float*)d_in[2];
    const float* memory = (const float*)d_in[3];
    const float* Wq = (const float*)d_in[4];
    const float* bq = (const float*)d_in[5];
    const float* Wk = (const float*)d_in[6];
    const float* bk = (const float*)d_in[7];
    const float* Wv = (const float*)d_in[8];
    const float* bv = (const float*)d_in[9];
    const float* Wo = (const float*)d_in[10];
    const float* bo = (const float*)d_in[11];
    float* out = (float*)d_out;

    float *Qp, *Kp, *Vp, *MK, *MV, *O;
    cudaGetSymbolAddress((void**)&Qp, g_Qp);
    cudaGetSymbolAddress((void**)&Kp, g_Kp);
    cudaGetSymbolAddress((void**)&Vp, g_Vp);
    cudaGetSymbolAddress((void**)&MK, g_MK);
    cudaGetSymbolAddress((void**)&MV, g_MV);
    cudaGetSymbolAddress((void**)&O,  g_O);

    __nv_bfloat16 *qh,*ql,*kh,*kl,*vh,*vl,*mh,*ml,*oh,*ol;
    __nv_bfloat16 *wqh,*wql,*wkh,*wkl,*wvh,*wvl,*woh,*wol;
    cudaGetSymbolAddress((void**)&qh, g_q_hi);  cudaGetSymbolAddress((void**)&ql, g_q_lo);
    cudaGetSymbolAddress((void**)&kh, g_k_hi);  cudaGetSymbolAddress((void**)&kl, g_k_lo);
    cudaGetSymbolAddress((void**)&vh, g_v_hi);  cudaGetSymbolAddress((void**)&vl, g_v_lo);
    cudaGetSymbolAddress((void**)&mh, g_m_hi);  cudaGetSymbolAddress((void**)&ml, g_m_lo);
    cudaGetSymbolAddress((void**)&oh, g_o_hi);  cudaGetSymbolAddress((void**)&ol, g_o_lo);
    cudaGetSymbolAddress((void**)&wqh, g_wq_hi); cudaGetSymbolAddress((void**)&wql, g_wq_lo);
    cudaGetSymbolAddress((void**)&wkh, g_wk_hi); cudaGetSymbolAddress((void**)&wkl, g_wk_lo);
    cudaGetSymbolAddress((void**)&wvh, g_wv_hi); cudaGetSymbolAddress((void**)&wvl, g_wv_lo);
    cudaGetSymbolAddress((void**)&woh, g_wo_hi); cudaGetSymbolAddress((void**)&wol, g_wo_lo);

    static const int SMEM_BYTES = 2 * GSTAGE;   // 64 KB
    cudaFuncSetAttribute(gemm_mma, cudaFuncAttributeMaxDynamicSharedMemorySize, SMEM_BYTES);

    const int NQ = BB * QQ * EE, NK = BB * KK * EE, NW = EE * EE;

    // fp32 -> bf16 hi/lo splits
    f32_to_bf16pair<<<NQ / 256, 256>>>(query,  qh, ql);
    f32_to_bf16pair<<<NK / 256, 256>>>(key,    kh, kl);
    f32_to_bf16pair<<<NK / 256, 256>>>(value,  vh, vl);
    f32_to_bf16pair<<<NQ / 256, 256>>>(memory, mh, ml);
    f32_to_bf16pair<<<NW / 256, 256>>>(Wq, wqh, wql);
    f32_to_bf16pair<<<NW / 256, 256>>>(Wk, wkh, wkl);
    f32_to_bf16pair<<<NW / 256, 256>>>(Wv, wvh, wvl);
    f32_to_bf16pair<<<NW / 256, 256>>>(Wo, woh, wol);

    // Projections on tensor cores (grid: x = 1024/128 = 8 col tiles, y = rows/128)
    gemm_mma<<<dim3(8, 16), 256, SMEM_BYTES>>>(qh, ql, wqh, wql, bq, Qp);
    gemm_mma<<<dim3(8, 32), 256, SMEM_BYTES>>>(kh, kl, wkh, wkl, bk, Kp);
    gemm_mma<<<dim3(8, 32), 256, SMEM_BYTES>>>(vh, vl, wvh, wvl, bv, Vp);
    gemm_mma<<<dim3(8, 16), 256, SMEM_BYTES>>>(mh, ml, wkh, wkl, bk, MK);
    gemm_mma<<<dim3(8, 16), 256, SMEM_BYTES>>>(mh, ml, wvh, wvl, bv, MV);

    // Attention
    attn_kernel<<<dim3(16, 64), 256>>>();

    // Output projection
    f32_to_bf16pair<<<NQ / 256, 256>>>(O, oh, ol);
    gemm_mma<<<dim3(8, 16), 256, SMEM_BYTES>>>(oh, ol, woh, wol, bo, out);
}